// round 1
// baseline (speedup 1.0000x reference)
#include <cuda_runtime.h>
#include <math.h>

// Problem constants (fixed shapes per reference)
#define NN 50000
#define EE 800000
#define HH 8
#define HC 256
#define SLOPE 0.2f

// ---------------- static device scratch (no allocations allowed) --------------
__device__ float g_h[NN * HC];        // projected features (x @ W) per layer
__device__ float g_o[NN * HC];        // layer output (input to next layer)
__device__ float g_als[NN * HH];      // per-node src attention logits
__device__ float g_ald[NN * HH];      // per-node dst attention logits
__device__ float g_we[HH];            // edge attention weight per head
__device__ int   g_rowptr[NN + 1];
__device__ int   g_cnt[NN];
__device__ int   g_tmp[NN];
__device__ int   g_esrc[EE];          // CSR-ordered source node per edge
__device__ float g_eea[EE];           // CSR-ordered edge attr per edge
__device__ float g_easum[NN];
__device__ float g_loopea[NN];        // self-loop edge attr (mean of incoming)
__device__ int   g_bsum[64];

// ---------------- CSR build ---------------------------------------------------
__global__ void k_init_counts() {
    int i = blockIdx.x * blockDim.x + threadIdx.x;
    if (i < NN) { g_cnt[i] = 0; g_tmp[i] = 0; g_easum[i] = 0.0f; }
}

__global__ void k_hist(const int* __restrict__ ei, const float* __restrict__ ea) {
    int e = blockIdx.x * blockDim.x + threadIdx.x;
    if (e < EE) {
        int d = ei[EE + e];
        atomicAdd(&g_cnt[d], 1);
        atomicAdd(&g_easum[d], ea[e]);
    }
}

__global__ void k_scan1() {
    __shared__ int s[1024];
    int tid = threadIdx.x;
    int i = blockIdx.x * 1024 + tid;
    int v = (i < NN) ? g_cnt[i] : 0;
    s[tid] = v;
    __syncthreads();
    for (int off = 1; off < 1024; off <<= 1) {
        int t = (tid >= off) ? s[tid - off] : 0;
        __syncthreads();
        s[tid] += t;
        __syncthreads();
    }
    if (i < NN) g_rowptr[i] = s[tid] - v;   // exclusive
    if (tid == 1023) g_bsum[blockIdx.x] = s[1023];
}

__global__ void k_scan2(int nblk) {
    if (threadIdx.x == 0 && blockIdx.x == 0) {
        int running = 0;
        for (int b = 0; b < nblk; b++) {
            int t = g_bsum[b];
            g_bsum[b] = running;
            running += t;
        }
        g_rowptr[NN] = EE;
    }
}

__global__ void k_scan3() {
    int i = blockIdx.x * blockDim.x + threadIdx.x;
    if (i < NN) g_rowptr[i] += g_bsum[i >> 10];
}

__global__ void k_build(const int* __restrict__ ei, const float* __restrict__ ea) {
    int e = blockIdx.x * blockDim.x + threadIdx.x;
    if (e < EE) {
        int d = ei[EE + e];
        int pos = g_rowptr[d] + atomicAdd(&g_tmp[d], 1);
        g_esrc[pos] = ei[e];
        g_eea[pos] = ea[e];
    }
}

__global__ void k_loopea() {
    int n = blockIdx.x * blockDim.x + threadIdx.x;
    if (n < NN) g_loopea[n] = g_easum[n] / fmaxf((float)g_cnt[n], 1.0f);
}

// ---------------- per-layer small kernels ------------------------------------
// w_e[h] = sum_c We[h,c]*ae[h,c]
__global__ void k_we(const float* __restrict__ We, const float* __restrict__ ae) {
    int tid = threadIdx.x;          // 256
    int w = tid >> 5, lane = tid & 31;
    float v = We[tid] * ae[tid];
    for (int o = 16; o > 0; o >>= 1) v += __shfl_xor_sync(0xffffffffu, v, o);
    if (lane == 0) g_we[w] = v;
}

// Layer-1 projection (K=4) fused with als/ald computation. One block per node.
__global__ void k_proj4(const float* __restrict__ x, const float* __restrict__ W,
                        const float* __restrict__ as_, const float* __restrict__ ad_) {
    int n = blockIdx.x;
    int tid = threadIdx.x;          // 256
    __shared__ float xs[4];
    if (tid < 4) xs[tid] = x[n * 4 + tid];
    __syncthreads();
    float v = xs[0] * W[0 * 256 + tid] + xs[1] * W[1 * 256 + tid]
            + xs[2] * W[2 * 256 + tid] + xs[3] * W[3 * 256 + tid];
    g_h[n * 256 + tid] = v;
    float s = v * as_[tid];
    float d = v * ad_[tid];
    for (int o = 16; o > 0; o >>= 1) {
        s += __shfl_xor_sync(0xffffffffu, s, o);
        d += __shfl_xor_sync(0xffffffffu, d, o);
    }
    if ((tid & 31) == 0) {
        g_als[n * 8 + (tid >> 5)] = s;
        g_ald[n * 8 + (tid >> 5)] = d;
    }
}

// als/ald from g_h (for layers 2,3). One block per node.
__global__ void k_nodeatt(const float* __restrict__ as_, const float* __restrict__ ad_) {
    int n = blockIdx.x;
    int tid = threadIdx.x;
    float v = g_h[n * 256 + tid];
    float s = v * as_[tid];
    float d = v * ad_[tid];
    for (int o = 16; o > 0; o >>= 1) {
        s += __shfl_xor_sync(0xffffffffu, s, o);
        d += __shfl_xor_sync(0xffffffffu, d, o);
    }
    if ((tid & 31) == 0) {
        g_als[n * 8 + (tid >> 5)] = s;
        g_ald[n * 8 + (tid >> 5)] = d;
    }
}

// ---------------- SGEMM: g_h = g_o @ W  ([M,256] x [256,256]) ----------------
__global__ void k_sgemm(const float* __restrict__ W, int M) {
    __shared__ float As[8][128];
    __shared__ float Bs[8][128];
    int tid = threadIdx.x;              // 256
    int rowBase = blockIdx.y * 128;
    int colBase = blockIdx.x * 128;
    int tx = tid & 15, ty = tid >> 4;

    float acc[8][8];
#pragma unroll
    for (int i = 0; i < 8; i++)
#pragma unroll
        for (int j = 0; j < 8; j++) acc[i][j] = 0.0f;

    int aRow = tid >> 1;
    int aCol = (tid & 1) * 4;
    int bRow = tid >> 5;
    int bCol = (tid & 31) * 4;
    const float* A = g_o;

    for (int k0 = 0; k0 < 256; k0 += 8) {
        float4 av = make_float4(0.f, 0.f, 0.f, 0.f);
        int gr = rowBase + aRow;
        if (gr < M) av = *(const float4*)(A + gr * 256 + k0 + aCol);
        As[aCol + 0][aRow] = av.x;
        As[aCol + 1][aRow] = av.y;
        As[aCol + 2][aRow] = av.z;
        As[aCol + 3][aRow] = av.w;
        float4 bv = *(const float4*)(W + (k0 + bRow) * 256 + colBase + bCol);
        *(float4*)&Bs[bRow][bCol] = bv;
        __syncthreads();
#pragma unroll
        for (int k = 0; k < 8; k++) {
            float ra[8], rb[8];
#pragma unroll
            for (int i = 0; i < 8; i++) ra[i] = As[k][ty * 8 + i];
#pragma unroll
            for (int j = 0; j < 8; j++) rb[j] = Bs[k][tx * 8 + j];
#pragma unroll
            for (int i = 0; i < 8; i++)
#pragma unroll
                for (int j = 0; j < 8; j++) acc[i][j] += ra[i] * rb[j];
        }
        __syncthreads();
    }
#pragma unroll
    for (int i = 0; i < 8; i++) {
        int gr = rowBase + ty * 8 + i;
        if (gr < M) {
            float4 v0 = make_float4(acc[i][0], acc[i][1], acc[i][2], acc[i][3]);
            float4 v1 = make_float4(acc[i][4], acc[i][5], acc[i][6], acc[i][7]);
            *(float4*)(g_h + gr * 256 + colBase + tx * 8) = v0;
            *(float4*)(g_h + gr * 256 + colBase + tx * 8 + 4) = v1;
        }
    }
}

// ---------------- fused attention + aggregation ------------------------------
// One warp per destination node. Two passes over its CSR edge list:
//   pass1: per-head max of leaky(logit)   (4-way edge parallel, 8 head lanes)
//   pass2: acc[c] += p * h[src,c], psum += p, then out = acc/psum + bias, ReLU
// If outp == nullptr, write to g_o, else to outp (d_out for layer 3).
__global__ void k_attn(const float* __restrict__ bias, float* __restrict__ outp,
                       int useLoop) {
    int warp = (blockIdx.x * blockDim.x + threadIdx.x) >> 5;
    if (warp >= NN) return;
    int n = warp;
    int l = threadIdx.x & 31;
    int head1 = l & 7, sub = l >> 3;    // pass1 mapping
    int head2 = l >> 2;                 // pass2 mapping (channels l*8..l*8+7)

    int start = g_rowptr[n], end = g_rowptr[n + 1];
    float le = useLoop ? g_loopea[n] : 0.0f;

    // ---- pass 1: per-head max ----
    float we1 = g_we[head1];
    float ald1 = g_ald[n * 8 + head1];
    float m = -INFINITY;
    if (useLoop) {
        float lg = g_als[n * 8 + head1] + ald1 + le * we1;
        m = (lg > 0.0f) ? lg : SLOPE * lg;
    }
    for (int i = start + sub; i < end; i += 4) {
        int s = g_esrc[i];
        float eav = g_eea[i];
        float lg = g_als[s * 8 + head1] + ald1 + eav * we1;
        lg = (lg > 0.0f) ? lg : SLOPE * lg;
        m = fmaxf(m, lg);
    }
    m = fmaxf(m, __shfl_xor_sync(0xffffffffu, m, 8));
    m = fmaxf(m, __shfl_xor_sync(0xffffffffu, m, 16));
    // now lane l holds the max for head (l&7)

    // ---- pass 2: weighted aggregation ----
    float we2 = g_we[head2];
    float ald2 = g_ald[n * 8 + head2];
    float m2 = __shfl_sync(0xffffffffu, m, head2);

    float acc[8] = {0.f, 0.f, 0.f, 0.f, 0.f, 0.f, 0.f, 0.f};
    float psum = 0.0f;

    if (useLoop) {
        float lg = g_als[n * 8 + head2] + ald2 + le * we2;
        lg = (lg > 0.0f) ? lg : SLOPE * lg;
        float p = __expf(lg - m2);
        psum += p;
        const float4* hv = (const float4*)(g_h + n * 256 + l * 8);
        float4 a = hv[0], b = hv[1];
        acc[0] += p * a.x; acc[1] += p * a.y; acc[2] += p * a.z; acc[3] += p * a.w;
        acc[4] += p * b.x; acc[5] += p * b.y; acc[6] += p * b.z; acc[7] += p * b.w;
    }
    for (int i = start; i < end; i++) {
        int s = g_esrc[i];
        float eav = g_eea[i];
        float lg = g_als[s * 8 + head2] + ald2 + eav * we2;
        lg = (lg > 0.0f) ? lg : SLOPE * lg;
        float p = __expf(lg - m2);
        psum += p;
        const float4* hv = (const float4*)(g_h + s * 256 + l * 8);
        float4 a = hv[0], b = hv[1];
        acc[0] += p * a.x; acc[1] += p * a.y; acc[2] += p * a.z; acc[3] += p * a.w;
        acc[4] += p * b.x; acc[5] += p * b.y; acc[6] += p * b.z; acc[7] += p * b.w;
    }

    float inv = 1.0f / (psum + 1e-16f);
    float* out = outp ? outp : g_o;
    const float* bp = bias + l * 8;
    float4 o0 = make_float4(fmaxf(acc[0] * inv + bp[0], 0.f),
                            fmaxf(acc[1] * inv + bp[1], 0.f),
                            fmaxf(acc[2] * inv + bp[2], 0.f),
                            fmaxf(acc[3] * inv + bp[3], 0.f));
    float4 o1 = make_float4(fmaxf(acc[4] * inv + bp[4], 0.f),
                            fmaxf(acc[5] * inv + bp[5], 0.f),
                            fmaxf(acc[6] * inv + bp[6], 0.f),
                            fmaxf(acc[7] * inv + bp[7], 0.f));
    *(float4*)(out + n * 256 + l * 8) = o0;
    *(float4*)(out + n * 256 + l * 8 + 4) = o1;
}

// ---------------- launch ------------------------------------------------------
extern "C" void kernel_launch(void* const* d_in, const int* in_sizes, int n_in,
                              void* d_out, int out_size) {
    const float* x  = (const float*)d_in[0];
    const int*   ei = (const int*)d_in[1];
    const float* ea = (const float*)d_in[2];
    const float* W1 = (const float*)d_in[3];
    const float* as1 = (const float*)d_in[4];
    const float* ad1 = (const float*)d_in[5];
    const float* We1 = (const float*)d_in[6];
    const float* ae1 = (const float*)d_in[7];
    const float* b1 = (const float*)d_in[8];
    const float* W2 = (const float*)d_in[9];
    const float* as2 = (const float*)d_in[10];
    const float* ad2 = (const float*)d_in[11];
    const float* We2 = (const float*)d_in[12];
    const float* ae2 = (const float*)d_in[13];
    const float* b2 = (const float*)d_in[14];
    const float* W3 = (const float*)d_in[15];
    const float* as3 = (const float*)d_in[16];
    const float* ad3 = (const float*)d_in[17];
    const float* We3 = (const float*)d_in[18];
    const float* ae3 = (const float*)d_in[19];
    const float* b3 = (const float*)d_in[20];
    float* out = (float*)d_out;

    const int nblkN = (NN + 255) / 256;
    const int nblkE = (EE + 255) / 256;
    const int scanBlk = (NN + 1023) / 1024;       // 49
    const int attnBlk = (NN * 32 + 255) / 256;    // 6250

    // --- CSR build (same every launch; edge structure is a fixed input) ---
    k_init_counts<<<nblkN, 256>>>();
    k_hist<<<nblkE, 256>>>(ei, ea);
    k_scan1<<<scanBlk, 1024>>>();
    k_scan2<<<1, 32>>>(scanBlk);
    k_scan3<<<scanBlk, 1024>>>();
    k_build<<<nblkE, 256>>>(ei, ea);
    k_loopea<<<nblkN, 256>>>();

    dim3 gGemm(2, (NN + 127) / 128);

    // --- layer 1 (no self loops) ---
    k_we<<<1, 256>>>(We1, ae1);
    k_proj4<<<NN, 256>>>(x, W1, as1, ad1);
    k_attn<<<attnBlk, 256>>>(b1, nullptr, 0);

    // --- layer 2 (self loops) ---
    k_we<<<1, 256>>>(We2, ae2);
    k_sgemm<<<gGemm, 256>>>(W2, NN);
    k_nodeatt<<<NN, 256>>>(as2, ad2);
    k_attn<<<attnBlk, 256>>>(b2, nullptr, 1);

    // --- layer 3 (self loops) -> d_out ---
    k_we<<<1, 256>>>(We3, ae3);
    k_sgemm<<<gGemm, 256>>>(W3, NN);
    k_nodeatt<<<NN, 256>>>(as3, ad3);
    k_attn<<<attnBlk, 256>>>(b3, out, 1);
}

// round 2
// speedup vs baseline: 1.1582x; 1.1582x over previous
#include <cuda_runtime.h>
#include <math.h>

// Problem constants (fixed shapes per reference)
#define NN 50000
#define EE 800000
#define HH 8
#define HC 256
#define SLOPE 0.2f

// ---------------- static device scratch (no allocations allowed) --------------
__device__ float g_h[NN * HC];        // projected features (x @ W) per layer
__device__ float g_o[NN * HC];        // layer output (input to next layer)
__device__ float g_als[NN * HH];      // per-node src attention logits
__device__ float g_ald[NN * HH];      // per-node dst attention logits
__device__ float g_we[HH];            // edge attention weight per head
__device__ float g_vs[4][8];          // layer-1 folded src attention (W1 . as)
__device__ float g_vd[4][8];          // layer-1 folded dst attention (W1 . ad)
__device__ int   g_rowptr[NN + 1];
__device__ int   g_cnt[NN];
__device__ int   g_tmp[NN];
__device__ int   g_esrc[EE];          // CSR-ordered source node per edge
__device__ float g_eea[EE];           // CSR-ordered edge attr per edge
__device__ float g_easum[NN];         // sum of incoming edge attr per node
__device__ int   g_bsum[64];

// ---------------- f32x2 packed math helpers (sm_103a) -------------------------
__device__ __forceinline__ unsigned long long splat2(float x) {
    unsigned long long r;
    asm("mov.b64 %0,{%1,%1};" : "=l"(r) : "f"(x));
    return r;
}
__device__ __forceinline__ void fma2(unsigned long long& d,
                                     unsigned long long a, unsigned long long b) {
    asm("fma.rn.f32x2 %0,%1,%2,%0;" : "+l"(d) : "l"(a), "l"(b));
}
__device__ __forceinline__ float2 unpack2(unsigned long long v) {
    float2 r;
    asm("mov.b64 {%0,%1},%2;" : "=f"(r.x), "=f"(r.y) : "l"(v));
    return r;
}

// ---------------- CSR build ---------------------------------------------------
__global__ void k_init_counts() {
    int i = blockIdx.x * blockDim.x + threadIdx.x;
    if (i < NN) { g_cnt[i] = 0; g_tmp[i] = 0; g_easum[i] = 0.0f; }
}

__global__ void k_hist(const int* __restrict__ ei, const float* __restrict__ ea) {
    int e = blockIdx.x * blockDim.x + threadIdx.x;
    if (e < EE) {
        int d = ei[EE + e];
        atomicAdd(&g_cnt[d], 1);
        atomicAdd(&g_easum[d], ea[e]);
    }
}

__global__ void k_scan1() {
    __shared__ int s[1024];
    int tid = threadIdx.x;
    int i = blockIdx.x * 1024 + tid;
    int v = (i < NN) ? g_cnt[i] : 0;
    s[tid] = v;
    __syncthreads();
    for (int off = 1; off < 1024; off <<= 1) {
        int t = (tid >= off) ? s[tid - off] : 0;
        __syncthreads();
        s[tid] += t;
        __syncthreads();
    }
    if (i < NN) g_rowptr[i] = s[tid] - v;   // exclusive within block
    if (tid == 1023) g_bsum[blockIdx.x] = s[1023];
}

__global__ void k_scan2(int nblk) {           // 64-thread parallel scan of block sums
    __shared__ int sh[64];
    int l = threadIdx.x;
    int v = (l < nblk) ? g_bsum[l] : 0;
    sh[l] = v;
    __syncthreads();
    for (int off = 1; off < 64; off <<= 1) {
        int t = (l >= off) ? sh[l - off] : 0;
        __syncthreads();
        sh[l] += t;
        __syncthreads();
    }
    if (l < nblk) g_bsum[l] = sh[l] - v;      // exclusive
    if (l == 0) g_rowptr[NN] = EE;
}

__global__ void k_scan3() {
    int i = blockIdx.x * blockDim.x + threadIdx.x;
    if (i < NN) g_rowptr[i] += g_bsum[i >> 10];
}

__global__ void k_build(const int* __restrict__ ei, const float* __restrict__ ea) {
    int e = blockIdx.x * blockDim.x + threadIdx.x;
    if (e < EE) {
        int d = ei[EE + e];
        int pos = g_rowptr[d] + atomicAdd(&g_tmp[d], 1);
        g_esrc[pos] = ei[e];
        g_eea[pos] = ea[e];
    }
}

// ---------------- layer-1 folded prep ----------------------------------------
// g_vs[k][h] = sum_c W1[k, h*32+c]*as[h,c]; g_vd likewise; g_we[h] = sum We*ae.
__global__ void k_prep1(const float* __restrict__ W1, const float* __restrict__ as_,
                        const float* __restrict__ ad_, const float* __restrict__ We,
                        const float* __restrict__ ae) {
    int t = threadIdx.x;               // 256
    int h = t >> 5, lane = t & 31;
    float asv = as_[t], adv = ad_[t];
#pragma unroll
    for (int k = 0; k < 4; k++) {
        float w = W1[k * 256 + t];
        float s = w * asv, d = w * adv;
        for (int o = 16; o > 0; o >>= 1) {
            s += __shfl_xor_sync(0xffffffffu, s, o);
            d += __shfl_xor_sync(0xffffffffu, d, o);
        }
        if (lane == 0) { g_vs[k][h] = s; g_vd[k][h] = d; }
    }
    float v = We[t] * ae[t];
    for (int o = 16; o > 0; o >>= 1) v += __shfl_xor_sync(0xffffffffu, v, o);
    if (lane == 0) g_we[h] = v;
}

// layer-1 node attention logits from raw x (rank-4 fold)
__global__ void k_nodeatt1(const float* __restrict__ x) {
    int idx = blockIdx.x * blockDim.x + threadIdx.x;
    if (idx >= NN * 8) return;
    int n = idx >> 3, h = idx & 7;
    float x0 = x[n * 4], x1 = x[n * 4 + 1], x2 = x[n * 4 + 2], x3 = x[n * 4 + 3];
    g_als[idx] = x0 * g_vs[0][h] + x1 * g_vs[1][h] + x2 * g_vs[2][h] + x3 * g_vs[3][h];
    g_ald[idx] = x0 * g_vd[0][h] + x1 * g_vd[1][h] + x2 * g_vd[2][h] + x3 * g_vd[3][h];
}

// ---------------- layer-1 fused attention (rank-4 aggregation) ----------------
// One warp per dst node. Lane l: head = l>>2, input-channel c = l&3.
// Online softmax over edges aggregating x[src] (4 floats/head), then expand
// agg @ W1 per head, add bias, ReLU -> g_o.
__global__ void __launch_bounds__(256) k_attn1(
    const float* __restrict__ x, const float* __restrict__ W1,
    const float* __restrict__ bias) {
    int warp = (blockIdx.x * blockDim.x + threadIdx.x) >> 5;
    if (warp >= NN) return;
    int n = warp;
    int l = threadIdx.x & 31;
    int head = l >> 2, c = l & 3;

    float we = g_we[head];
    float ald = g_ald[n * 8 + head];
    int start = g_rowptr[n], end = g_rowptr[n + 1];

    float m = -INFINITY, psum = 0.0f, acc = 0.0f;
    int i = start;
    for (; i + 2 <= end; i += 2) {
        int s0 = g_esrc[i], s1 = g_esrc[i + 1];
        float e0 = g_eea[i], e1 = g_eea[i + 1];
        float al0 = g_als[s0 * 8 + head], al1 = g_als[s1 * 8 + head];
        float xv0 = x[s0 * 4 + c], xv1 = x[s1 * 4 + c];
        float lg0 = al0 + ald + e0 * we; lg0 = (lg0 > 0.f) ? lg0 : SLOPE * lg0;
        float lg1 = al1 + ald + e1 * we; lg1 = (lg1 > 0.f) ? lg1 : SLOPE * lg1;
        float nm = fmaxf(m, fmaxf(lg0, lg1));
        float sc = __expf(m - nm);
        float p0 = __expf(lg0 - nm);
        float p1 = __expf(lg1 - nm);
        psum = psum * sc + p0 + p1;
        acc = acc * sc + p0 * xv0 + p1 * xv1;
        m = nm;
    }
    if (i < end) {
        int s0 = g_esrc[i];
        float e0 = g_eea[i];
        float lg0 = g_als[s0 * 8 + head] + ald + e0 * we;
        lg0 = (lg0 > 0.f) ? lg0 : SLOPE * lg0;
        float nm = fmaxf(m, lg0);
        float sc = __expf(m - nm);
        float p0 = __expf(lg0 - nm);
        psum = psum * sc + p0;
        acc = acc * sc + p0 * x[s0 * 4 + c];
    }

    float inv = 1.0f / (psum + 1e-16f);
    float aggv = acc * inv;
    int base = l & ~3;
    float a0 = __shfl_sync(0xffffffffu, aggv, base);
    float a1 = __shfl_sync(0xffffffffu, aggv, base + 1);
    float a2 = __shfl_sync(0xffffffffu, aggv, base + 2);
    float a3 = __shfl_sync(0xffffffffu, aggv, base + 3);

    float o[8];
#pragma unroll
    for (int cc = 0; cc < 8; cc++) {
        int ch = l * 8 + cc;
        float v = fmaf(a0, W1[ch],
                  fmaf(a1, W1[256 + ch],
                  fmaf(a2, W1[512 + ch],
                  fmaf(a3, W1[768 + ch], bias[ch]))));
        o[cc] = fmaxf(v, 0.0f);
    }
    *(float4*)(g_o + n * 256 + l * 8)     = make_float4(o[0], o[1], o[2], o[3]);
    *(float4*)(g_o + n * 256 + l * 8 + 4) = make_float4(o[4], o[5], o[6], o[7]);
}

// ---------------- node attention logits for layers 2,3 (warp per node) --------
// Last block (blockIdx.x == gridDim.x-1) computes g_we instead.
__global__ void k_nodeatt(const float* __restrict__ as_, const float* __restrict__ ad_,
                          const float* __restrict__ We, const float* __restrict__ ae) {
    if (blockIdx.x == gridDim.x - 1) {
        int t = threadIdx.x;
        int h = t >> 5, lane = t & 31;
        float v = We[t] * ae[t];
        for (int o = 16; o > 0; o >>= 1) v += __shfl_xor_sync(0xffffffffu, v, o);
        if (lane == 0) g_we[h] = v;
        return;
    }
    int warp = (blockIdx.x * blockDim.x + threadIdx.x) >> 5;
    if (warp >= NN) return;
    int n = warp;
    int l = threadIdx.x & 31;
    const float4* hv = (const float4*)(g_h + n * 256 + l * 8);
    float4 a = hv[0], b = hv[1];
    const float* asp = as_ + l * 8;
    const float* adp = ad_ + l * 8;
    float s = a.x * asp[0] + a.y * asp[1] + a.z * asp[2] + a.w * asp[3]
            + b.x * asp[4] + b.y * asp[5] + b.z * asp[6] + b.w * asp[7];
    float d = a.x * adp[0] + a.y * adp[1] + a.z * adp[2] + a.w * adp[3]
            + b.x * adp[4] + b.y * adp[5] + b.z * adp[6] + b.w * adp[7];
    s += __shfl_xor_sync(0xffffffffu, s, 1);
    s += __shfl_xor_sync(0xffffffffu, s, 2);
    d += __shfl_xor_sync(0xffffffffu, d, 1);
    d += __shfl_xor_sync(0xffffffffu, d, 2);
    if ((l & 3) == 0) {
        g_als[n * 8 + (l >> 2)] = s;
        g_ald[n * 8 + (l >> 2)] = d;
    }
}

// ---------------- SGEMM: g_h = g_o @ W  ([M,256] x [256,256], f32x2 packed) ---
__global__ void __launch_bounds__(256) k_sgemm(const float* __restrict__ W, int M) {
    __shared__ float As[8][128];
    __shared__ float Bs[8][128];
    int tid = threadIdx.x;              // 256
    int rowBase = blockIdx.y * 128;
    int colBase = blockIdx.x * 128;
    int tx = tid & 15, ty = tid >> 4;

    unsigned long long acc2[8][4];
#pragma unroll
    for (int i = 0; i < 8; i++)
#pragma unroll
        for (int j = 0; j < 4; j++) acc2[i][j] = 0ull;   // packed {0.f,0.f}

    int aRow = tid >> 1;
    int aCol = (tid & 1) * 4;
    int bRow = tid >> 5;
    int bCol = (tid & 31) * 4;
    const float* A = g_o;

    for (int k0 = 0; k0 < 256; k0 += 8) {
        float4 av = make_float4(0.f, 0.f, 0.f, 0.f);
        int gr = rowBase + aRow;
        if (gr < M) av = *(const float4*)(A + gr * 256 + k0 + aCol);
        As[aCol + 0][aRow] = av.x;
        As[aCol + 1][aRow] = av.y;
        As[aCol + 2][aRow] = av.z;
        As[aCol + 3][aRow] = av.w;
        float4 bv = *(const float4*)(W + (k0 + bRow) * 256 + colBase + bCol);
        *(float4*)&Bs[bRow][bCol] = bv;
        __syncthreads();
#pragma unroll
        for (int k = 0; k < 8; k++) {
            unsigned long long ra2[8], rb2[4];
#pragma unroll
            for (int i = 0; i < 4; i++) {
                float2 rp = *(const float2*)&As[k][ty * 8 + i * 2];
                ra2[i * 2]     = splat2(rp.x);
                ra2[i * 2 + 1] = splat2(rp.y);
            }
#pragma unroll
            for (int j = 0; j < 4; j++)
                rb2[j] = *(const unsigned long long*)&Bs[k][tx * 8 + j * 2];
#pragma unroll
            for (int i = 0; i < 8; i++)
#pragma unroll
                for (int j = 0; j < 4; j++) fma2(acc2[i][j], ra2[i], rb2[j]);
        }
        __syncthreads();
    }
#pragma unroll
    for (int i = 0; i < 8; i++) {
        int gr = rowBase + ty * 8 + i;
        if (gr < M) {
            float2 p0 = unpack2(acc2[i][0]);
            float2 p1 = unpack2(acc2[i][1]);
            float2 p2 = unpack2(acc2[i][2]);
            float2 p3 = unpack2(acc2[i][3]);
            *(float4*)(g_h + gr * 256 + colBase + tx * 8)     = make_float4(p0.x, p0.y, p1.x, p1.y);
            *(float4*)(g_h + gr * 256 + colBase + tx * 8 + 4) = make_float4(p2.x, p2.y, p3.x, p3.y);
        }
    }
}

// ---------------- fused attention + aggregation (layers 2,3, self-loops) ------
// One warp per dst node, online softmax, single pass over CSR edge list.
// Lane l: head = l>>2, channels l*8 .. l*8+7.
__global__ void __launch_bounds__(256) k_attn(const float* __restrict__ bias,
                                              float* __restrict__ outp) {
    int warp = (blockIdx.x * blockDim.x + threadIdx.x) >> 5;
    if (warp >= NN) return;
    int n = warp;
    int l = threadIdx.x & 31;
    int head = l >> 2;

    float we = g_we[head];
    float ald = g_ald[n * 8 + head];
    int start = g_rowptr[n], end = g_rowptr[n + 1];

    // self-loop init (fill_value='mean')
    float le = g_easum[n] / fmaxf((float)(end - start), 1.0f);
    float lg = g_als[n * 8 + head] + ald + le * we;
    lg = (lg > 0.f) ? lg : SLOPE * lg;
    float m = lg, psum = 1.0f;
    float acc[8];
    {
        const float4* hv = (const float4*)(g_h + n * 256 + l * 8);
        float4 a = hv[0], b = hv[1];
        acc[0] = a.x; acc[1] = a.y; acc[2] = a.z; acc[3] = a.w;
        acc[4] = b.x; acc[5] = b.y; acc[6] = b.z; acc[7] = b.w;
    }

    int i = start;
    for (; i + 2 <= end; i += 2) {
        int s0 = g_esrc[i], s1 = g_esrc[i + 1];
        float e0 = g_eea[i], e1 = g_eea[i + 1];
        float al0 = g_als[s0 * 8 + head], al1 = g_als[s1 * 8 + head];
        const float4* h0 = (const float4*)(g_h + s0 * 256 + l * 8);
        const float4* h1 = (const float4*)(g_h + s1 * 256 + l * 8);
        float4 a0 = h0[0], b0 = h0[1];
        float4 a1 = h1[0], b1 = h1[1];
        float lg0 = al0 + ald + e0 * we; lg0 = (lg0 > 0.f) ? lg0 : SLOPE * lg0;
        float lg1 = al1 + ald + e1 * we; lg1 = (lg1 > 0.f) ? lg1 : SLOPE * lg1;
        float nm = fmaxf(m, fmaxf(lg0, lg1));
        float sc = __expf(m - nm);
        float p0 = __expf(lg0 - nm);
        float p1 = __expf(lg1 - nm);
        psum = psum * sc + p0 + p1;
        acc[0] = acc[0] * sc + p0 * a0.x + p1 * a1.x;
        acc[1] = acc[1] * sc + p0 * a0.y + p1 * a1.y;
        acc[2] = acc[2] * sc + p0 * a0.z + p1 * a1.z;
        acc[3] = acc[3] * sc + p0 * a0.w + p1 * a1.w;
        acc[4] = acc[4] * sc + p0 * b0.x + p1 * b1.x;
        acc[5] = acc[5] * sc + p0 * b0.y + p1 * b1.y;
        acc[6] = acc[6] * sc + p0 * b0.z + p1 * b1.z;
        acc[7] = acc[7] * sc + p0 * b0.w + p1 * b1.w;
        m = nm;
    }
    if (i < end) {
        int s0 = g_esrc[i];
        float e0 = g_eea[i];
        float lg0 = g_als[s0 * 8 + head] + ald + e0 * we;
        lg0 = (lg0 > 0.f) ? lg0 : SLOPE * lg0;
        const float4* h0 = (const float4*)(g_h + s0 * 256 + l * 8);
        float4 a0 = h0[0], b0 = h0[1];
        float nm = fmaxf(m, lg0);
        float sc = __expf(m - nm);
        float p0 = __expf(lg0 - nm);
        psum = psum * sc + p0;
        acc[0] = acc[0] * sc + p0 * a0.x;
        acc[1] = acc[1] * sc + p0 * a0.y;
        acc[2] = acc[2] * sc + p0 * a0.z;
        acc[3] = acc[3] * sc + p0 * a0.w;
        acc[4] = acc[4] * sc + p0 * b0.x;
        acc[5] = acc[5] * sc + p0 * b0.y;
        acc[6] = acc[6] * sc + p0 * b0.z;
        acc[7] = acc[7] * sc + p0 * b0.w;
    }

    float inv = 1.0f / (psum + 1e-16f);
    const float* bp = bias + l * 8;
    float4 o0 = make_float4(fmaxf(acc[0] * inv + bp[0], 0.f),
                            fmaxf(acc[1] * inv + bp[1], 0.f),
                            fmaxf(acc[2] * inv + bp[2], 0.f),
                            fmaxf(acc[3] * inv + bp[3], 0.f));
    float4 o1 = make_float4(fmaxf(acc[4] * inv + bp[4], 0.f),
                            fmaxf(acc[5] * inv + bp[5], 0.f),
                            fmaxf(acc[6] * inv + bp[6], 0.f),
                            fmaxf(acc[7] * inv + bp[7], 0.f));
    *(float4*)(outp + n * 256 + l * 8)     = o0;
    *(float4*)(outp + n * 256 + l * 8 + 4) = o1;
}

// ---------------- launch ------------------------------------------------------
extern "C" void kernel_launch(void* const* d_in, const int* in_sizes, int n_in,
                              void* d_out, int out_size) {
    const float* x   = (const float*)d_in[0];
    const int*   ei  = (const int*)d_in[1];
    const float* ea  = (const float*)d_in[2];
    const float* W1  = (const float*)d_in[3];
    const float* as1 = (const float*)d_in[4];
    const float* ad1 = (const float*)d_in[5];
    const float* We1 = (const float*)d_in[6];
    const float* ae1 = (const float*)d_in[7];
    const float* b1  = (const float*)d_in[8];
    const float* W2  = (const float*)d_in[9];
    const float* as2 = (const float*)d_in[10];
    const float* ad2 = (const float*)d_in[11];
    const float* We2 = (const float*)d_in[12];
    const float* ae2 = (const float*)d_in[13];
    const float* b2  = (const float*)d_in[14];
    const float* W3  = (const float*)d_in[15];
    const float* as3 = (const float*)d_in[16];
    const float* ad3 = (const float*)d_in[17];
    const float* We3 = (const float*)d_in[18];
    const float* ae3 = (const float*)d_in[19];
    const float* b3  = (const float*)d_in[20];
    float* out = (float*)d_out;

    // retrieve g_o pointer for layer outputs via device symbol is implicit:
    // kernels use the __device__ globals directly.

    const int nblkN   = (NN + 255) / 256;
    const int nblkE   = (EE + 255) / 256;
    const int scanBlk = (NN + 1023) / 1024;        // 49
    const int attnBlk = (NN * 32 + 255) / 256;     // 6250
    const int na1Blk  = (NN * 8 + 255) / 256;      // 1563

    // --- CSR build ---
    k_init_counts<<<nblkN, 256>>>();
    k_hist<<<nblkE, 256>>>(ei, ea);
    k_scan1<<<scanBlk, 1024>>>();
    k_scan2<<<1, 64>>>(scanBlk);
    k_scan3<<<scanBlk, 1024>>>();
    k_build<<<nblkE, 256>>>(ei, ea);

    dim3 gGemm(2, (NN + 127) / 128);

    // --- layer 1 (no self loops, rank-4 fold) ---
    k_prep1<<<1, 256>>>(W1, as1, ad1, We1, ae1);
    k_nodeatt1<<<na1Blk, 256>>>(x);
    k_attn1<<<attnBlk, 256>>>(x, W1, b1);

    // --- layer 2 (self loops) ---
    k_sgemm<<<gGemm, 256>>>(W2, NN);
    k_nodeatt<<<attnBlk + 1, 256>>>(as2, ad2, We2, ae2);
    {
        float* g_o_ptr = nullptr;
        cudaGetSymbolAddress((void**)&g_o_ptr, g_o);
        k_attn<<<attnBlk, 256>>>(b2, g_o_ptr);
    }

    // --- layer 3 (self loops) -> d_out ---
    k_sgemm<<<gGemm, 256>>>(W3, NN);
    k_nodeatt<<<attnBlk + 1, 256>>>(as3, ad3, We3, ae3);
    k_attn<<<attnBlk, 256>>>(b3, out);
}

// round 3
// speedup vs baseline: 1.6714x; 1.4431x over previous
#include <cuda_runtime.h>
#include <math.h>

// Problem constants (fixed shapes per reference)
#define NN 50000
#define EE 800000
#define HH 8
#define HC 256
#define SLOPE 0.2f

// ---------------- static device scratch (no allocations allowed) --------------
__device__ float g_h[NN * HC];        // projected features (x @ W) per layer
__device__ float g_o[NN * HC];        // layer output (input to next layer)
__device__ float g_als[NN * HH];      // per-node src attention logits
__device__ float g_ald[NN * HH];      // per-node dst attention logits
__device__ float g_we[HH];            // edge attention weight per head
__device__ float g_vs[4][8];          // layer-1 folded src attention (W1 . as)
__device__ float g_vd[4][8];          // layer-1 folded dst attention (W1 . ad)
__device__ int   g_rowptr[NN + 1];
__device__ int   g_cnt[NN];
__device__ int   g_tmp[NN];
__device__ int   g_esrc[EE];          // CSR-ordered source node per edge
__device__ float g_eea[EE];           // CSR-ordered edge attr per edge
__device__ float g_easum[NN];         // sum of incoming edge attr per node
__device__ int   g_bsum[64];

// ---------------- helpers ------------------------------------------------------
__device__ __forceinline__ float to_tf32(float x) {
    unsigned r;
    asm("cvt.rn.tf32.f32 %0,%1;" : "=r"(r) : "f"(x));
    return __uint_as_float(r);
}
__device__ __forceinline__ void mma_tf32(float* c, const unsigned* a, const unsigned* b) {
    asm volatile(
        "mma.sync.aligned.m16n8k8.row.col.f32.tf32.tf32.f32 "
        "{%0,%1,%2,%3},{%4,%5,%6,%7},{%8,%9},{%0,%1,%2,%3};"
        : "+f"(c[0]), "+f"(c[1]), "+f"(c[2]), "+f"(c[3])
        : "r"(a[0]), "r"(a[1]), "r"(a[2]), "r"(a[3]), "r"(b[0]), "r"(b[1]));
}

// ---------------- CSR build ---------------------------------------------------
__global__ void k_init_counts() {
    int i = blockIdx.x * blockDim.x + threadIdx.x;
    if (i < NN) { g_cnt[i] = 0; g_tmp[i] = 0; g_easum[i] = 0.0f; }
}

__global__ void k_hist(const int* __restrict__ ei, const float* __restrict__ ea) {
    int e = blockIdx.x * blockDim.x + threadIdx.x;
    if (e < EE) {
        int d = ei[EE + e];
        atomicAdd(&g_cnt[d], 1);
        atomicAdd(&g_easum[d], ea[e]);
    }
}

__global__ void k_scan1() {
    __shared__ int s[1024];
    int tid = threadIdx.x;
    int i = blockIdx.x * 1024 + tid;
    int v = (i < NN) ? g_cnt[i] : 0;
    s[tid] = v;
    __syncthreads();
    for (int off = 1; off < 1024; off <<= 1) {
        int t = (tid >= off) ? s[tid - off] : 0;
        __syncthreads();
        s[tid] += t;
        __syncthreads();
    }
    if (i < NN) g_rowptr[i] = s[tid] - v;   // exclusive within block
    if (tid == 1023) g_bsum[blockIdx.x] = s[1023];   // block total
}

// scan3 also absorbs the cross-block prefix (scan2): one warp sums bsum[0..bid)
__global__ void k_scan3() {
    __shared__ int s_off;
    int bid = blockIdx.x;
    int t = threadIdx.x;
    if (t < 32) {
        int v = 0;
        for (int b = t; b < bid; b += 32) v += g_bsum[b];
        for (int o = 16; o > 0; o >>= 1) v += __shfl_xor_sync(0xffffffffu, v, o);
        if (t == 0) s_off = v;
    }
    if (bid == 0 && t == 0) g_rowptr[NN] = EE;
    __syncthreads();
    int i = bid * 1024 + t;
    if (i < NN) g_rowptr[i] += s_off;
}

__global__ void k_build(const int* __restrict__ ei, const float* __restrict__ ea) {
    int e = blockIdx.x * blockDim.x + threadIdx.x;
    if (e < EE) {
        int d = ei[EE + e];
        int pos = g_rowptr[d] + atomicAdd(&g_tmp[d], 1);
        g_esrc[pos] = ei[e];
        g_eea[pos] = ea[e];
    }
}

// ---------------- layer-1 folded prep ----------------------------------------
__global__ void k_prep1(const float* __restrict__ W1, const float* __restrict__ as_,
                        const float* __restrict__ ad_, const float* __restrict__ We,
                        const float* __restrict__ ae) {
    int t = threadIdx.x;               // 256
    int h = t >> 5, lane = t & 31;
    float asv = as_[t], adv = ad_[t];
#pragma unroll
    for (int k = 0; k < 4; k++) {
        float w = W1[k * 256 + t];
        float s = w * asv, d = w * adv;
        for (int o = 16; o > 0; o >>= 1) {
            s += __shfl_xor_sync(0xffffffffu, s, o);
            d += __shfl_xor_sync(0xffffffffu, d, o);
        }
        if (lane == 0) { g_vs[k][h] = s; g_vd[k][h] = d; }
    }
    float v = We[t] * ae[t];
    for (int o = 16; o > 0; o >>= 1) v += __shfl_xor_sync(0xffffffffu, v, o);
    if (lane == 0) g_we[h] = v;
}

// layer-1 node attention logits from raw x (rank-4 fold)
__global__ void k_nodeatt1(const float* __restrict__ x) {
    int idx = blockIdx.x * blockDim.x + threadIdx.x;
    if (idx >= NN * 8) return;
    int n = idx >> 3, h = idx & 7;
    float x0 = x[n * 4], x1 = x[n * 4 + 1], x2 = x[n * 4 + 2], x3 = x[n * 4 + 3];
    g_als[idx] = x0 * g_vs[0][h] + x1 * g_vs[1][h] + x2 * g_vs[2][h] + x3 * g_vs[3][h];
    g_ald[idx] = x0 * g_vd[0][h] + x1 * g_vd[1][h] + x2 * g_vd[2][h] + x3 * g_vd[3][h];
}

// ---------------- layer-1 fused attention (rank-4 aggregation) ----------------
__global__ void __launch_bounds__(256) k_attn1(
    const float* __restrict__ x, const float* __restrict__ W1,
    const float* __restrict__ bias) {
    int warp = (blockIdx.x * blockDim.x + threadIdx.x) >> 5;
    if (warp >= NN) return;
    int n = warp;
    int l = threadIdx.x & 31;
    int head = l >> 2, c = l & 3;

    float we = g_we[head];
    float ald = g_ald[n * 8 + head];
    int start = g_rowptr[n], end = g_rowptr[n + 1];

    float m = -INFINITY, psum = 0.0f, acc = 0.0f;
    int i = start;
    for (; i + 2 <= end; i += 2) {
        int s0 = g_esrc[i], s1 = g_esrc[i + 1];
        float e0 = g_eea[i], e1 = g_eea[i + 1];
        float al0 = g_als[s0 * 8 + head], al1 = g_als[s1 * 8 + head];
        float xv0 = x[s0 * 4 + c], xv1 = x[s1 * 4 + c];
        float lg0 = al0 + ald + e0 * we; lg0 = (lg0 > 0.f) ? lg0 : SLOPE * lg0;
        float lg1 = al1 + ald + e1 * we; lg1 = (lg1 > 0.f) ? lg1 : SLOPE * lg1;
        float nm = fmaxf(m, fmaxf(lg0, lg1));
        float sc = __expf(m - nm);
        float p0 = __expf(lg0 - nm);
        float p1 = __expf(lg1 - nm);
        psum = psum * sc + p0 + p1;
        acc = acc * sc + p0 * xv0 + p1 * xv1;
        m = nm;
    }
    if (i < end) {
        int s0 = g_esrc[i];
        float e0 = g_eea[i];
        float lg0 = g_als[s0 * 8 + head] + ald + e0 * we;
        lg0 = (lg0 > 0.f) ? lg0 : SLOPE * lg0;
        float nm = fmaxf(m, lg0);
        float sc = __expf(m - nm);
        float p0 = __expf(lg0 - nm);
        psum = psum * sc + p0;
        acc = acc * sc + p0 * x[s0 * 4 + c];
    }

    float inv = 1.0f / (psum + 1e-16f);
    float aggv = acc * inv;
    int base = l & ~3;
    float a0 = __shfl_sync(0xffffffffu, aggv, base);
    float a1 = __shfl_sync(0xffffffffu, aggv, base + 1);
    float a2 = __shfl_sync(0xffffffffu, aggv, base + 2);
    float a3 = __shfl_sync(0xffffffffu, aggv, base + 3);

    float o[8];
#pragma unroll
    for (int cc = 0; cc < 8; cc++) {
        int ch = l * 8 + cc;
        float v = fmaf(a0, W1[ch],
                  fmaf(a1, W1[256 + ch],
                  fmaf(a2, W1[512 + ch],
                  fmaf(a3, W1[768 + ch], bias[ch]))));
        o[cc] = fmaxf(v, 0.0f);
    }
    *(float4*)(g_o + n * 256 + l * 8)     = make_float4(o[0], o[1], o[2], o[3]);
    *(float4*)(g_o + n * 256 + l * 8 + 4) = make_float4(o[4], o[5], o[6], o[7]);
}

// ---------------- node attention logits for layers 2,3 (warp per node) --------
__global__ void k_nodeatt(const float* __restrict__ as_, const float* __restrict__ ad_,
                          const float* __restrict__ We, const float* __restrict__ ae) {
    if (blockIdx.x == gridDim.x - 1) {
        int t = threadIdx.x;
        int h = t >> 5, lane = t & 31;
        float v = We[t] * ae[t];
        for (int o = 16; o > 0; o >>= 1) v += __shfl_xor_sync(0xffffffffu, v, o);
        if (lane == 0) g_we[h] = v;
        return;
    }
    int warp = (blockIdx.x * blockDim.x + threadIdx.x) >> 5;
    if (warp >= NN) return;
    int n = warp;
    int l = threadIdx.x & 31;
    const float4* hv = (const float4*)(g_h + n * 256 + l * 8);
    float4 a = hv[0], b = hv[1];
    const float* asp = as_ + l * 8;
    const float* adp = ad_ + l * 8;
    float s = a.x * asp[0] + a.y * asp[1] + a.z * asp[2] + a.w * asp[3]
            + b.x * asp[4] + b.y * asp[5] + b.z * asp[6] + b.w * asp[7];
    float d = a.x * adp[0] + a.y * adp[1] + a.z * adp[2] + a.w * adp[3]
            + b.x * adp[4] + b.y * adp[5] + b.z * adp[6] + b.w * adp[7];
    s += __shfl_xor_sync(0xffffffffu, s, 1);
    s += __shfl_xor_sync(0xffffffffu, s, 2);
    d += __shfl_xor_sync(0xffffffffu, d, 1);
    d += __shfl_xor_sync(0xffffffffu, d, 2);
    if ((l & 3) == 0) {
        g_als[n * 8 + (l >> 2)] = s;
        g_ald[n * 8 + (l >> 2)] = d;
    }
}

// ---------------- TF32 tensor-core GEMM: g_h = g_o @ W  ([M,256]x[256,256]) ---
// Block tile 128x128, K-chunk 32, 8 warps in 4x2 (warp tile 32x64).
// Smem stride 136 words (8 mod 32) -> conflict-free fragment LDS.
__global__ void __launch_bounds__(256, 2) k_gemm_tf32(const float* __restrict__ W,
                                                      int M) {
    __shared__ float As[32][136];   // [k][row]
    __shared__ float Bs[32][136];   // [k][col]
    const float* A = g_o;
    float* C = g_h;

    int tid = threadIdx.x;
    int rowBase = blockIdx.y * 128;
    int colBase = blockIdx.x * 128;

    int wid = tid >> 5, lane = tid & 31;
    int wm = wid & 3, wn = wid >> 2;            // 4x2 warp grid
    int gid = lane >> 2, tg = lane & 3;

    // gmem load mapping
    int arow = tid >> 1, ak4 = (tid & 1) * 4;   // A: 128 rows x 8 k per (tid&1) pair
    int bk = tid >> 3,  bn4 = (tid & 7) * 4;    // B: 32 k rows x 32 n per group
    bool aval = (rowBase + arow) < M;
    const float* Aptr = A + (rowBase + arow) * 256 + ak4;
    const float* Wp   = W + bk * 256 + colBase + bn4;

    float acc[2][8][4];
#pragma unroll
    for (int i = 0; i < 2; i++)
#pragma unroll
        for (int j = 0; j < 8; j++)
#pragma unroll
            for (int q = 0; q < 4; q++) acc[i][j][q] = 0.0f;

    float4 ar[4], br[4];
    // prefetch chunk 0
#pragma unroll
    for (int u = 0; u < 4; u++) {
        ar[u] = aval ? *(const float4*)(Aptr + u * 8)
                     : make_float4(0.f, 0.f, 0.f, 0.f);
        br[u] = *(const float4*)(Wp + u * 32);
    }

#pragma unroll
    for (int it = 0; it < 8; it++) {
        // stage current chunk into smem (tf32-rounded)
#pragma unroll
        for (int u = 0; u < 4; u++) {
            int kb = u * 8 + ak4;
            As[kb + 0][arow] = to_tf32(ar[u].x);
            As[kb + 1][arow] = to_tf32(ar[u].y);
            As[kb + 2][arow] = to_tf32(ar[u].z);
            As[kb + 3][arow] = to_tf32(ar[u].w);
            float4 bv = br[u];
            bv.x = to_tf32(bv.x); bv.y = to_tf32(bv.y);
            bv.z = to_tf32(bv.z); bv.w = to_tf32(bv.w);
            *(float4*)&Bs[bk][u * 32 + bn4] = bv;
        }
        __syncthreads();
        // prefetch next chunk
        if (it < 7) {
            const float* Ap2 = Aptr + (it + 1) * 32;
            const float* Wp2 = Wp + (it + 1) * 32 * 256;
#pragma unroll
            for (int u = 0; u < 4; u++) {
                ar[u] = aval ? *(const float4*)(Ap2 + u * 8)
                             : make_float4(0.f, 0.f, 0.f, 0.f);
                br[u] = *(const float4*)(Wp2 + u * 32);
            }
        }
        // compute 4 k-steps
#pragma unroll
        for (int kt = 0; kt < 4; kt++) {
            int k0 = kt * 8 + tg;
            unsigned a[2][4];
#pragma unroll
            for (int i = 0; i < 2; i++) {
                int rb = wm * 32 + i * 16 + gid;
                a[i][0] = __float_as_uint(As[k0][rb]);
                a[i][1] = __float_as_uint(As[k0][rb + 8]);
                a[i][2] = __float_as_uint(As[k0 + 4][rb]);
                a[i][3] = __float_as_uint(As[k0 + 4][rb + 8]);
            }
            unsigned b[8][2];
#pragma unroll
            for (int j = 0; j < 8; j++) {
                int cb = wn * 64 + j * 8 + gid;
                b[j][0] = __float_as_uint(Bs[k0][cb]);
                b[j][1] = __float_as_uint(Bs[k0 + 4][cb]);
            }
#pragma unroll
            for (int i = 0; i < 2; i++)
#pragma unroll
                for (int j = 0; j < 8; j++) mma_tf32(acc[i][j], a[i], b[j]);
        }
        __syncthreads();
    }

    // epilogue
#pragma unroll
    for (int i = 0; i < 2; i++) {
        int r0 = rowBase + wm * 32 + i * 16 + gid;
        int r1 = r0 + 8;
#pragma unroll
        for (int j = 0; j < 8; j++) {
            int col = colBase + wn * 64 + j * 8 + tg * 2;
            if (r0 < M) *(float2*)(C + r0 * 256 + col) = make_float2(acc[i][j][0], acc[i][j][1]);
            if (r1 < M) *(float2*)(C + r1 * 256 + col) = make_float2(acc[i][j][2], acc[i][j][3]);
        }
    }
}

// ---------------- fused attention + aggregation (layers 2,3, self-loops) ------
__global__ void __launch_bounds__(256) k_attn(const float* __restrict__ bias,
                                              float* __restrict__ outp) {
    int warp = (blockIdx.x * blockDim.x + threadIdx.x) >> 5;
    if (warp >= NN) return;
    int n = warp;
    int l = threadIdx.x & 31;
    int head = l >> 2;

    float we = g_we[head];
    float ald = g_ald[n * 8 + head];
    int start = g_rowptr[n], end = g_rowptr[n + 1];

    // self-loop init (fill_value='mean')
    float le = g_easum[n] / fmaxf((float)(end - start), 1.0f);
    float lg = g_als[n * 8 + head] + ald + le * we;
    lg = (lg > 0.f) ? lg : SLOPE * lg;
    float m = lg, psum = 1.0f;
    float acc[8];
    {
        const float4* hv = (const float4*)(g_h + n * 256 + l * 8);
        float4 a = hv[0], b = hv[1];
        acc[0] = a.x; acc[1] = a.y; acc[2] = a.z; acc[3] = a.w;
        acc[4] = b.x; acc[5] = b.y; acc[6] = b.z; acc[7] = b.w;
    }

    int i = start;
    for (; i + 2 <= end; i += 2) {
        int s0 = g_esrc[i], s1 = g_esrc[i + 1];
        float e0 = g_eea[i], e1 = g_eea[i + 1];
        float al0 = g_als[s0 * 8 + head], al1 = g_als[s1 * 8 + head];
        const float4* h0 = (const float4*)(g_h + s0 * 256 + l * 8);
        const float4* h1 = (const float4*)(g_h + s1 * 256 + l * 8);
        float4 a0 = h0[0], b0 = h0[1];
        float4 a1 = h1[0], b1 = h1[1];
        float lg0 = al0 + ald + e0 * we; lg0 = (lg0 > 0.f) ? lg0 : SLOPE * lg0;
        float lg1 = al1 + ald + e1 * we; lg1 = (lg1 > 0.f) ? lg1 : SLOPE * lg1;
        float nm = fmaxf(m, fmaxf(lg0, lg1));
        float sc = __expf(m - nm);
        float p0 = __expf(lg0 - nm);
        float p1 = __expf(lg1 - nm);
        psum = psum * sc + p0 + p1;
        acc[0] = acc[0] * sc + p0 * a0.x + p1 * a1.x;
        acc[1] = acc[1] * sc + p0 * a0.y + p1 * a1.y;
        acc[2] = acc[2] * sc + p0 * a0.z + p1 * a1.z;
        acc[3] = acc[3] * sc + p0 * a0.w + p1 * a1.w;
        acc[4] = acc[4] * sc + p0 * b0.x + p1 * b1.x;
        acc[5] = acc[5] * sc + p0 * b0.y + p1 * b1.y;
        acc[6] = acc[6] * sc + p0 * b0.z + p1 * b1.z;
        acc[7] = acc[7] * sc + p0 * b0.w + p1 * b1.w;
        m = nm;
    }
    if (i < end) {
        int s0 = g_esrc[i];
        float e0 = g_eea[i];
        float lg0 = g_als[s0 * 8 + head] + ald + e0 * we;
        lg0 = (lg0 > 0.f) ? lg0 : SLOPE * lg0;
        const float4* h0 = (const float4*)(g_h + s0 * 256 + l * 8);
        float4 a0 = h0[0], b0 = h0[1];
        float nm = fmaxf(m, lg0);
        float sc = __expf(m - nm);
        float p0 = __expf(lg0 - nm);
        psum = psum * sc + p0;
        acc[0] = acc[0] * sc + p0 * a0.x;
        acc[1] = acc[1] * sc + p0 * a0.y;
        acc[2] = acc[2] * sc + p0 * a0.z;
        acc[3] = acc[3] * sc + p0 * a0.w;
        acc[4] = acc[4] * sc + p0 * b0.x;
        acc[5] = acc[5] * sc + p0 * b0.y;
        acc[6] = acc[6] * sc + p0 * b0.z;
        acc[7] = acc[7] * sc + p0 * b0.w;
    }

    float inv = 1.0f / (psum + 1e-16f);
    const float* bp = bias + l * 8;
    float4 o0 = make_float4(fmaxf(acc[0] * inv + bp[0], 0.f),
                            fmaxf(acc[1] * inv + bp[1], 0.f),
                            fmaxf(acc[2] * inv + bp[2], 0.f),
                            fmaxf(acc[3] * inv + bp[3], 0.f));
    float4 o1 = make_float4(fmaxf(acc[4] * inv + bp[4], 0.f),
                            fmaxf(acc[5] * inv + bp[5], 0.f),
                            fmaxf(acc[6] * inv + bp[6], 0.f),
                            fmaxf(acc[7] * inv + bp[7], 0.f));
    *(float4*)(outp + n * 256 + l * 8)     = o0;
    *(float4*)(outp + n * 256 + l * 8 + 4) = o1;
}

// ---------------- launch ------------------------------------------------------
extern "C" void kernel_launch(void* const* d_in, const int* in_sizes, int n_in,
                              void* d_out, int out_size) {
    const float* x   = (const float*)d_in[0];
    const int*   ei  = (const int*)d_in[1];
    const float* ea  = (const float*)d_in[2];
    const float* W1  = (const float*)d_in[3];
    const float* as1 = (const float*)d_in[4];
    const float* ad1 = (const float*)d_in[5];
    const float* We1 = (const float*)d_in[6];
    const float* ae1 = (const float*)d_in[7];
    const float* b1  = (const float*)d_in[8];
    const float* W2  = (const float*)d_in[9];
    const float* as2 = (const float*)d_in[10];
    const float* ad2 = (const float*)d_in[11];
    const float* We2 = (const float*)d_in[12];
    const float* ae2 = (const float*)d_in[13];
    const float* b2  = (const float*)d_in[14];
    const float* W3  = (const float*)d_in[15];
    const float* as3 = (const float*)d_in[16];
    const float* ad3 = (const float*)d_in[17];
    const float* We3 = (const float*)d_in[18];
    const float* ae3 = (const float*)d_in[19];
    const float* b3  = (const float*)d_in[20];
    float* out = (float*)d_out;

    const int nblkN   = (NN + 255) / 256;
    const int nblkE   = (EE + 255) / 256;
    const int scanBlk = (NN + 1023) / 1024;        // 49
    const int attnBlk = (NN * 32 + 255) / 256;     // 6250
    const int na1Blk  = (NN * 8 + 255) / 256;      // 1563

    // --- CSR build ---
    k_init_counts<<<nblkN, 256>>>();
    k_hist<<<nblkE, 256>>>(ei, ea);
    k_scan1<<<scanBlk, 1024>>>();
    k_scan3<<<scanBlk, 1024>>>();
    k_build<<<nblkE, 256>>>(ei, ea);

    dim3 gGemm(2, (NN + 127) / 128);

    // --- layer 1 (no self loops, rank-4 fold) ---
    k_prep1<<<1, 256>>>(W1, as1, ad1, We1, ae1);
    k_nodeatt1<<<na1Blk, 256>>>(x);
    k_attn1<<<attnBlk, 256>>>(x, W1, b1);

    // --- layer 2 (self loops) ---
    k_gemm_tf32<<<gGemm, 256>>>(W2, NN);
    k_nodeatt<<<attnBlk + 1, 256>>>(as2, ad2, We2, ae2);
    {
        float* g_o_ptr = nullptr;
        cudaGetSymbolAddress((void**)&g_o_ptr, g_o);
        k_attn<<<attnBlk, 256>>>(b2, g_o_ptr);
    }

    // --- layer 3 (self loops) -> d_out ---
    k_gemm_tf32<<<gGemm, 256>>>(W3, NN);
    k_nodeatt<<<attnBlk + 1, 256>>>(as3, ad3, We3, ae3);
    k_attn<<<attnBlk, 256>>>(b3, out);
}